// round 1
// baseline (speedup 1.0000x reference)
#include <cuda_runtime.h>
#include <cuda_bf16.h>

// Problem constants
#define B_   4
#define N_   2048
#define DIM_ 1024
#define H_   16
#define HD_  64
#define E3_  (3 * DIM_)        // 3072
#define M_   (B_ * N_)         // 8192
#define SCALE_ 0.125f          // 1/sqrt(64)

// Scratch: q/k/v in [B, H, N, HD] layout (q pre-scaled)
__device__ float g_q[B_ * H_ * N_ * HD_];
__device__ float g_k[B_ * H_ * N_ * HD_];
__device__ float g_v[B_ * H_ * N_ * HD_];

// ---------------------------------------------------------------------------
// Kernel 1: fused QKV projection
//   C[m][e] = sum_d X[m][d] * W[e][d] + bias[e]   (NT sgemm)
//   scatter into g_q (scaled), g_k, g_v with [B,H,N,HD] layout.
// 128x128 block tile, BK=8, 256 threads, 8x8 per-thread microtile.
// ---------------------------------------------------------------------------
__global__ __launch_bounds__(256, 2) void qkv_gemm_kernel(
    const float* __restrict__ X,
    const float* __restrict__ W,
    const float* __restrict__ bias)
{
    __shared__ float As[8][132];  // transposed [k][m], pad 132 -> conflict-free
    __shared__ float Bs[8][132];  // transposed [k][e]

    const int tid = threadIdx.x;
    const int tx  = tid & 15;     // 0..15 -> e microtile
    const int ty  = tid >> 4;     // 0..15 -> m microtile
    const int lr  = tid >> 1;     // 0..127 load row
    const int lc4 = (tid & 1) * 4;

    const int mBase = blockIdx.y * 128;
    const int eBase = blockIdx.x * 128;

    const float* Ap = X + (size_t)(mBase + lr) * DIM_ + lc4;
    const float* Bp = W + (size_t)(eBase + lr) * DIM_ + lc4;

    float acc[8][8];
    #pragma unroll
    for (int i = 0; i < 8; i++)
        #pragma unroll
        for (int j = 0; j < 8; j++) acc[i][j] = 0.0f;

    for (int kt = 0; kt < DIM_; kt += 8) {
        float4 a4 = *(const float4*)(Ap + kt);
        float4 b4 = *(const float4*)(Bp + kt);
        __syncthreads();
        As[lc4 + 0][lr] = a4.x; As[lc4 + 1][lr] = a4.y;
        As[lc4 + 2][lr] = a4.z; As[lc4 + 3][lr] = a4.w;
        Bs[lc4 + 0][lr] = b4.x; Bs[lc4 + 1][lr] = b4.y;
        Bs[lc4 + 2][lr] = b4.z; Bs[lc4 + 3][lr] = b4.w;
        __syncthreads();

        #pragma unroll
        for (int k = 0; k < 8; k++) {
            float4 a0 = *(const float4*)&As[k][ty * 8];
            float4 a1 = *(const float4*)&As[k][ty * 8 + 4];
            float4 b0 = *(const float4*)&Bs[k][tx * 8];
            float4 b1 = *(const float4*)&Bs[k][tx * 8 + 4];
            float av[8] = {a0.x, a0.y, a0.z, a0.w, a1.x, a1.y, a1.z, a1.w};
            float bv[8] = {b0.x, b0.y, b0.z, b0.w, b1.x, b1.y, b1.z, b1.w};
            #pragma unroll
            for (int i = 0; i < 8; i++)
                #pragma unroll
                for (int j = 0; j < 8; j++)
                    acc[i][j] = fmaf(av[i], bv[j], acc[i][j]);
        }
    }

    // Epilogue: bias + scale + scatter. e0..e0+7 stay within one (t,h) block
    // since both DIM_ and HD_ are multiples of 8.
    const int e0  = eBase + tx * 8;
    const int t   = e0 >> 10;          // 0=q 1=k 2=v
    const int rem = e0 & (DIM_ - 1);
    const int h   = rem >> 6;
    const int hd0 = rem & (HD_ - 1);
    float* dst = (t == 0) ? g_q : ((t == 1) ? g_k : g_v);
    const float scale = (t == 0) ? SCALE_ : 1.0f;

    float bb[8];
    #pragma unroll
    for (int j = 0; j < 8; j++) bb[j] = bias[e0 + j];

    #pragma unroll
    for (int i = 0; i < 8; i++) {
        int m  = mBase + ty * 8 + i;
        int bi = m >> 11;              // / N_
        int n  = m & (N_ - 1);
        float* p = dst + ((((size_t)bi * H_ + h) * N_ + n) * HD_ + hd0);
        float4 r0, r1;
        r0.x = (acc[i][0] + bb[0]) * scale;
        r0.y = (acc[i][1] + bb[1]) * scale;
        r0.z = (acc[i][2] + bb[2]) * scale;
        r0.w = (acc[i][3] + bb[3]) * scale;
        r1.x = (acc[i][4] + bb[4]) * scale;
        r1.y = (acc[i][5] + bb[5]) * scale;
        r1.z = (acc[i][6] + bb[6]) * scale;
        r1.w = (acc[i][7] + bb[7]) * scale;
        *(float4*)p       = r0;
        *(float4*)(p + 4) = r1;
    }
}

// ---------------------------------------------------------------------------
// Kernel 2: flash attention, fp32.
// grid = (N/64, B*H). block = 256 threads.
// Per block: 64 queries, loop over 32 key tiles of 64.
// Microtile: thread (ty=tid/16, tx=tid%15) owns S[4q x 4k] then O[4q x 4d].
// Online softmax state (m, l) replicated across the 16 tx lanes via shfl.
// ---------------------------------------------------------------------------
#define TSTR 68   // padded smem row stride (keeps float4 alignment, no conflicts)

__device__ __forceinline__ void load_tile_T(float* dst, const float* g, int tid)
{
    // 64x64 tile, global row stride 64 -> transposed dst [d][row], stride TSTR
    #pragma unroll
    for (int s = 0; s < 4; s++) {
        int idx = tid + s * 256;       // float4 slot 0..1023
        int row = idx >> 4;
        int c4  = (idx & 15) << 2;
        float4 v = *(const float4*)(g + row * HD_ + c4);
        dst[(c4 + 0) * TSTR + row] = v.x;
        dst[(c4 + 1) * TSTR + row] = v.y;
        dst[(c4 + 2) * TSTR + row] = v.z;
        dst[(c4 + 3) * TSTR + row] = v.w;
    }
}

__device__ __forceinline__ void load_tile(float* dst, const float* g, int tid)
{
    // direct copy, dst stride 64
    #pragma unroll
    for (int s = 0; s < 4; s++) {
        int idx = tid + s * 256;
        int row = idx >> 4;
        int c4  = (idx & 15) << 2;
        *(float4*)(dst + row * HD_ + c4) = *(const float4*)(g + row * HD_ + c4);
    }
}

__global__ __launch_bounds__(256, 3) void attn_kernel(float* __restrict__ out)
{
    extern __shared__ float sm[];
    float* Qt = sm;                     // [64][TSTR] transposed: Qt[d][q]
    float* Kt = Qt + 64 * TSTR;         // [64][TSTR] transposed: Kt[d][k]
    float* Ps = Kt + 64 * TSTR;         // [64][TSTR] : Ps[k][q]
    float* Vs = Ps + 64 * TSTR;         // [64][64]   : Vs[k][d]

    const int tid = threadIdx.x;
    const int tx  = tid & 15;           // key / out-dim microtile
    const int ty  = tid >> 4;           // query microtile
    const int bh  = blockIdx.y;
    const int bi  = bh >> 4;
    const int h   = bh & 15;
    const int q0  = blockIdx.x * 64;

    const float* Qg = g_q + (size_t)bh * N_ * HD_;
    const float* Kg = g_k + (size_t)bh * N_ * HD_;
    const float* Vg = g_v + (size_t)bh * N_ * HD_;

    load_tile_T(Qt, Qg + (size_t)q0 * HD_, tid);

    float o[4][4];
    float m[4], l[4];
    #pragma unroll
    for (int i = 0; i < 4; i++) {
        m[i] = -1e30f; l[i] = 0.0f;
        #pragma unroll
        for (int j = 0; j < 4; j++) o[i][j] = 0.0f;
    }

    for (int kt = 0; kt < N_ / 64; kt++) {
        __syncthreads();   // prev iteration done reading Kt/Vs; Qt ready (iter 0)
        load_tile_T(Kt, Kg + (size_t)kt * 64 * HD_, tid);
        load_tile  (Vs, Vg + (size_t)kt * 64 * HD_, tid);
        __syncthreads();

        // S = Q K^T  (4x4 per thread)
        float s[4][4];
        #pragma unroll
        for (int i = 0; i < 4; i++)
            #pragma unroll
            for (int j = 0; j < 4; j++) s[i][j] = 0.0f;

        #pragma unroll 16
        for (int d = 0; d < HD_; d++) {
            float4 a = *(const float4*)(Qt + d * TSTR + 4 * ty);
            float4 b = *(const float4*)(Kt + d * TSTR + 4 * tx);
            float av[4] = {a.x, a.y, a.z, a.w};
            float bv[4] = {b.x, b.y, b.z, b.w};
            #pragma unroll
            for (int i = 0; i < 4; i++)
                #pragma unroll
                for (int j = 0; j < 4; j++)
                    s[i][j] = fmaf(av[i], bv[j], s[i][j]);
        }

        // online softmax (row stats replicated across the 16 tx lanes)
        float corr[4];
        float p[4][4];
        #pragma unroll
        for (int i = 0; i < 4; i++) {
            float lm = fmaxf(fmaxf(s[i][0], s[i][1]), fmaxf(s[i][2], s[i][3]));
            #pragma unroll
            for (int off = 1; off < 16; off <<= 1)
                lm = fmaxf(lm, __shfl_xor_sync(0xffffffffu, lm, off));
            float mn = fmaxf(m[i], lm);
            corr[i] = __expf(m[i] - mn);
            m[i] = mn;
            float rs = 0.0f;
            #pragma unroll
            for (int j = 0; j < 4; j++) {
                p[i][j] = __expf(s[i][j] - mn);
                rs += p[i][j];
            }
            #pragma unroll
            for (int off = 1; off < 16; off <<= 1)
                rs += __shfl_xor_sync(0xffffffffu, rs, off);
            l[i] = l[i] * corr[i] + rs;
        }

        // write P to shared: Ps[k][q]
        #pragma unroll
        for (int j = 0; j < 4; j++) {
            float4 r = {p[0][j], p[1][j], p[2][j], p[3][j]};
            *(float4*)(Ps + (4 * tx + j) * TSTR + 4 * ty) = r;
        }
        __syncthreads();

        // O = O*corr + P V
        #pragma unroll
        for (int i = 0; i < 4; i++)
            #pragma unroll
            for (int j = 0; j < 4; j++) o[i][j] *= corr[i];

        #pragma unroll 16
        for (int k = 0; k < 64; k++) {
            float4 a = *(const float4*)(Ps + k * TSTR + 4 * ty);
            float4 b = *(const float4*)(Vs + k * HD_ + 4 * tx);
            float av[4] = {a.x, a.y, a.z, a.w};
            float bv[4] = {b.x, b.y, b.z, b.w};
            #pragma unroll
            for (int i = 0; i < 4; i++)
                #pragma unroll
                for (int j = 0; j < 4; j++)
                    o[i][j] = fmaf(av[i], bv[j], o[i][j]);
        }
    }

    // normalize + write out[b][n][h*64 + d]
    #pragma unroll
    for (int i = 0; i < 4; i++) {
        int n = q0 + 4 * ty + i;
        float inv = 1.0f / l[i];
        float4 r = {o[i][0] * inv, o[i][1] * inv, o[i][2] * inv, o[i][3] * inv};
        float* p = out + (((size_t)bi * N_ + n) * DIM_ + h * HD_ + 4 * tx);
        *(float4*)p = r;
    }
}

// ---------------------------------------------------------------------------
extern "C" void kernel_launch(void* const* d_in, const int* in_sizes, int n_in,
                              void* d_out, int out_size)
{
    const float* x    = (const float*)d_in[0];   // [B,N,DIM]
    const float* wqkv = (const float*)d_in[1];   // [3*DIM, DIM]
    const float* bqkv = (const float*)d_in[2];   // [3*DIM]
    float* out = (float*)d_out;                  // [B,N,DIM]

    const int attn_smem = (3 * 64 * TSTR + 64 * HD_) * (int)sizeof(float); // 68608 B
    cudaFuncSetAttribute(attn_kernel,
                         cudaFuncAttributeMaxDynamicSharedMemorySize, attn_smem);

    dim3 ggrid(E3_ / 128, M_ / 128);   // (24, 64)
    qkv_gemm_kernel<<<ggrid, 256>>>(x, wqkv, bqkv);

    dim3 agrid(N_ / 64, B_ * H_);      // (32, 64)
    attn_kernel<<<agrid, 256, attn_smem>>>(out);
}

// round 4
// speedup vs baseline: 2.8629x; 2.8629x over previous
#include <cuda_runtime.h>
#include <cstdint>

#define B_   4
#define N_   2048
#define DIM_ 1024
#define H_   16
#define HD_  64
#define E3_  3072
#define M_   8192
#define SCALE_ 0.125f

// Scratch (static device arrays; no allocation)
__device__ float g_xr[(size_t)M_ * DIM_];     // tf32-rounded X
__device__ float g_wr[(size_t)E3_ * DIM_];    // tf32-rounded W
__device__ float g_q[(size_t)B_ * H_ * N_ * HD_];
__device__ float g_k[(size_t)B_ * H_ * N_ * HD_];
__device__ float g_v[(size_t)B_ * H_ * N_ * HD_];

// ---------------------------------------------------------------------------
// helpers
// ---------------------------------------------------------------------------
__device__ __forceinline__ float tf32r(float x) {
    uint32_t u;
    asm("cvt.rna.tf32.f32 %0, %1;" : "=r"(u) : "f"(x));
    return __uint_as_float(u);
}
__device__ __forceinline__ uint32_t smem_u32(const void* p) {
    uint32_t a;
    asm("{ .reg .u64 t; cvta.to.shared.u64 t, %1; cvt.u32.u64 %0, t; }"
        : "=r"(a) : "l"(p));
    return a;
}
__device__ __forceinline__ void cpasync16(uint32_t dst, const void* src) {
    asm volatile("cp.async.cg.shared.global [%0], [%1], 16;"
                 :: "r"(dst), "l"(src) : "memory");
}
// d = a(16x8) * b(8x8) + c ; tf32 inputs, f32 accum
__device__ __forceinline__ void mma8(float* d,
                                     uint32_t a0, uint32_t a1, uint32_t a2, uint32_t a3,
                                     uint32_t b0, uint32_t b1) {
    asm volatile(
        "mma.sync.aligned.m16n8k8.row.col.f32.tf32.tf32.f32 "
        "{%0,%1,%2,%3}, {%4,%5,%6,%7}, {%8,%9}, {%0,%1,%2,%3};"
        : "+f"(d[0]), "+f"(d[1]), "+f"(d[2]), "+f"(d[3])
        : "r"(a0), "r"(a1), "r"(a2), "r"(a3), "r"(b0), "r"(b1));
}
__device__ __forceinline__ uint32_t f2u(float x) { return __float_as_uint(x); }

// ---------------------------------------------------------------------------
// Kernel 0: round fp32 -> tf32 (RN)
// ---------------------------------------------------------------------------
__global__ void round_tf32_kernel(const float4* __restrict__ in,
                                  float4* __restrict__ out, int n4) {
    int i = blockIdx.x * blockDim.x + threadIdx.x;
    if (i >= n4) return;
    float4 v = in[i];
    v.x = tf32r(v.x); v.y = tf32r(v.y); v.z = tf32r(v.z); v.w = tf32r(v.w);
    out[i] = v;
}

// ---------------------------------------------------------------------------
// Kernel 1: QKV projection, mma.sync tf32.
// C[m][e] = sum_d Xr[m][d]*Wr[e][d] + bias[e] -> scatter g_q/g_k/g_v (tf32-rounded)
// CTA 128x128, BK=32, 256 thr, 8 warps (2m x 4n), warp tile 64x32.
// smem rows padded to stride 36 floats -> all fragment LDS conflict-free.
// ---------------------------------------------------------------------------
#define GSTR 36
#define G_TILE (128 * GSTR)                 // floats per (A or B) buffer
#define G_SMEM_BYTES (4 * G_TILE * 4)       // As0,As1,Bs0,Bs1

__global__ __launch_bounds__(256) void qkv_mma_kernel(
    const float* __restrict__ Xr, const float* __restrict__ Wr,
    const float* __restrict__ bias)
{
    extern __shared__ float smg[];
    float* As[2] = { smg,              smg + G_TILE };
    float* Bs[2] = { smg + 2 * G_TILE, smg + 3 * G_TILE };
    const uint32_t sbase = smem_u32(smg);

    const int tid  = threadIdx.x;
    const int wid  = tid >> 5;
    const int lane = tid & 31;
    const int g    = lane >> 2;
    const int t    = lane & 3;
    const int warpM = (wid >> 2) * 64;
    const int warpN = (wid & 3) * 32;
    const int mBase = blockIdx.y * 128;
    const int eBase = blockIdx.x * 128;

    const int lrow = tid >> 1;        // 0..127
    const int lhalf = tid & 1;        // 16-float halves

    // async stage loader: stage s covers k0 = s*32
    auto load_stage = [&](int buf, int s) {
        const int k0 = s * 32;
        const float* ax = Xr + (size_t)(mBase + lrow) * DIM_ + k0 + lhalf * 16;
        const float* bx = Wr + (size_t)(eBase + lrow) * DIM_ + k0 + lhalf * 16;
        uint32_t da = sbase + (uint32_t)(((buf ? G_TILE : 0) + lrow * GSTR + lhalf * 16) * 4);
        uint32_t db = sbase + (uint32_t)(((2 * G_TILE + (buf ? G_TILE : 0)) + lrow * GSTR + lhalf * 16) * 4);
        #pragma unroll
        for (int c = 0; c < 4; c++) cpasync16(da + c * 16, ax + c * 4);
        #pragma unroll
        for (int c = 0; c < 4; c++) cpasync16(db + c * 16, bx + c * 4);
        asm volatile("cp.async.commit_group;" ::: "memory");
    };

    float acc[4][4][4];
    #pragma unroll
    for (int i = 0; i < 4; i++)
        #pragma unroll
        for (int j = 0; j < 4; j++)
            #pragma unroll
            for (int r = 0; r < 4; r++) acc[i][j][r] = 0.0f;

    load_stage(0, 0);
    load_stage(1, 1);

    for (int s = 0; s < DIM_ / 32; s++) {
        const int buf = s & 1;
        if (s < DIM_ / 32 - 1) asm volatile("cp.async.wait_group 1;" ::: "memory");
        else                   asm volatile("cp.async.wait_group 0;" ::: "memory");
        __syncthreads();

        const float* A = As[buf];
        const float* Bsm = Bs[buf];
        #pragma unroll
        for (int ks = 0; ks < 4; ks++) {
            uint32_t af[4][4];
            #pragma unroll
            for (int mt = 0; mt < 4; mt++) {
                const int r = warpM + mt * 16 + g;
                const int kk = ks * 8 + t;
                af[mt][0] = f2u(A[r * GSTR + kk]);
                af[mt][1] = f2u(A[(r + 8) * GSTR + kk]);
                af[mt][2] = f2u(A[r * GSTR + kk + 4]);
                af[mt][3] = f2u(A[(r + 8) * GSTR + kk + 4]);
            }
            #pragma unroll
            for (int nt = 0; nt < 4; nt++) {
                const int n = warpN + nt * 8 + g;
                const int kk = ks * 8 + t;
                uint32_t b0 = f2u(Bsm[n * GSTR + kk]);
                uint32_t b1 = f2u(Bsm[n * GSTR + kk + 4]);
                #pragma unroll
                for (int mt = 0; mt < 4; mt++)
                    mma8(acc[mt][nt], af[mt][0], af[mt][1], af[mt][2], af[mt][3], b0, b1);
            }
        }
        __syncthreads();
        if (s + 2 < DIM_ / 32) load_stage(buf, s + 2);
    }

    // epilogue: bias + scale + tf32 round + scatter (float2 stores)
    #pragma unroll
    for (int nt = 0; nt < 4; nt++) {
        const int c0  = eBase + warpN + nt * 8 + 2 * t;
        const int tsel = c0 >> 10;
        const int rem  = c0 & (DIM_ - 1);
        const int h    = rem >> 6;
        const int hd   = rem & (HD_ - 1);
        float* dst = (tsel == 0) ? g_q : ((tsel == 1) ? g_k : g_v);
        const float sc = (tsel == 0) ? SCALE_ : 1.0f;
        const float bb0 = __ldg(bias + c0);
        const float bb1 = __ldg(bias + c0 + 1);
        #pragma unroll
        for (int mt = 0; mt < 4; mt++) {
            const int r0 = mBase + warpM + mt * 16 + g;
            #pragma unroll
            for (int half = 0; half < 2; half++) {
                const int row = r0 + half * 8;
                const int bi  = row >> 11;
                const int n   = row & (N_ - 1);
                float2 v;
                v.x = tf32r((acc[mt][nt][half * 2 + 0] + bb0) * sc);
                v.y = tf32r((acc[mt][nt][half * 2 + 1] + bb1) * sc);
                *(float2*)(dst + ((((size_t)bi * H_ + h) * N_ + n) * HD_ + hd)) = v;
            }
        }
    }
}

// ---------------------------------------------------------------------------
// Kernel 2: flash attention on mma.sync tf32.
// grid (N/128, B*H), 256 thr, 8 warps x 16 q-rows. Key tile 64.
// smem: Qs[128][68], Ks[64][68], Vs[64][72], Ps[128][68]
// ---------------------------------------------------------------------------
#define QSTR 68
#define KSTR 68
#define VSTR 72
#define PSTR 68
#define OFF_K (128 * QSTR)
#define OFF_V (OFF_K + 64 * KSTR)
#define OFF_P (OFF_V + 64 * VSTR)
#define ATT_SMEM ((OFF_P + 128 * PSTR) * 4)

__global__ __launch_bounds__(256) void attn_kernel3(float* __restrict__ out)
{
    extern __shared__ float sm[];
    float* Qs = sm;
    float* Ks = sm + OFF_K;
    float* Vs = sm + OFF_V;
    float* Ps = sm + OFF_P;

    const int tid  = threadIdx.x;
    const int wid  = tid >> 5;
    const int lane = tid & 31;
    const int g    = lane >> 2;
    const int t    = lane & 3;
    const int warpQ = wid * 16;

    const int bh = blockIdx.y;
    const int bi = bh >> 4;
    const int h  = bh & 15;
    const int q0 = blockIdx.x * 128;

    const float* Qg = g_q + (size_t)bh * N_ * HD_ + (size_t)q0 * HD_;
    const float* Kg = g_k + (size_t)bh * N_ * HD_;
    const float* Vg = g_v + (size_t)bh * N_ * HD_;

    // load Q 128x64 -> Qs stride 68
    #pragma unroll
    for (int s = 0; s < 8; s++) {
        int slot = tid + s * 256;
        int row = slot >> 4;
        int c4  = (slot & 15) << 2;
        *(float4*)(Qs + row * QSTR + c4) = *(const float4*)(Qg + row * HD_ + c4);
    }

    float o[8][4];
    #pragma unroll
    for (int nt = 0; nt < 8; nt++)
        #pragma unroll
        for (int r = 0; r < 4; r++) o[nt][r] = 0.0f;
    float m0 = -1e30f, m1 = -1e30f, l0 = 0.0f, l1 = 0.0f;

    for (int kt = 0; kt < N_ / 64; kt++) {
        __syncthreads();
        // load K,V 64x64 tiles
        #pragma unroll
        for (int s = 0; s < 4; s++) {
            int slot = tid + s * 256;
            int row = slot >> 4;
            int c4  = (slot & 15) << 2;
            const float* kp = Kg + (size_t)(kt * 64 + row) * HD_ + c4;
            const float* vp = Vg + (size_t)(kt * 64 + row) * HD_ + c4;
            *(float4*)(Ks + row * KSTR + c4) = *(const float4*)kp;
            *(float4*)(Vs + row * VSTR + c4) = *(const float4*)vp;
        }
        __syncthreads();

        // stage 1: S = Q K^T  (warp: 16q x 64k)
        float s_[8][4];
        #pragma unroll
        for (int nt = 0; nt < 8; nt++)
            #pragma unroll
            for (int r = 0; r < 4; r++) s_[nt][r] = 0.0f;

        #pragma unroll
        for (int ks = 0; ks < 8; ks++) {
            const int kk = ks * 8 + t;
            const int r  = warpQ + g;
            uint32_t a0 = f2u(Qs[r * QSTR + kk]);
            uint32_t a1 = f2u(Qs[(r + 8) * QSTR + kk]);
            uint32_t a2 = f2u(Qs[r * QSTR + kk + 4]);
            uint32_t a3 = f2u(Qs[(r + 8) * QSTR + kk + 4]);
            #pragma unroll
            for (int nt = 0; nt < 8; nt++) {
                const int n = nt * 8 + g;
                uint32_t b0 = f2u(Ks[n * KSTR + kk]);
                uint32_t b1 = f2u(Ks[n * KSTR + kk + 4]);
                mma8(s_[nt], a0, a1, a2, a3, b0, b1);
            }
        }

        // online softmax: rows g (regs 0,1) and g+8 (regs 2,3)
        float mx0 = -1e30f, mx1 = -1e30f;
        #pragma unroll
        for (int nt = 0; nt < 8; nt++) {
            mx0 = fmaxf(mx0, fmaxf(s_[nt][0], s_[nt][1]));
            mx1 = fmaxf(mx1, fmaxf(s_[nt][2], s_[nt][3]));
        }
        mx0 = fmaxf(mx0, __shfl_xor_sync(0xffffffffu, mx0, 1));
        mx0 = fmaxf(mx0, __shfl_xor_sync(0xffffffffu, mx0, 2));
        mx1 = fmaxf(mx1, __shfl_xor_sync(0xffffffffu, mx1, 1));
        mx1 = fmaxf(mx1, __shfl_xor_sync(0xffffffffu, mx1, 2));
        const float nm0 = fmaxf(m0, mx0);
        const float nm1 = fmaxf(m1, mx1);
        const float corr0 = __expf(m0 - nm0);
        const float corr1 = __expf(m1 - nm1);
        m0 = nm0; m1 = nm1;

        float rs0 = 0.0f, rs1 = 0.0f;
        #pragma unroll
        for (int nt = 0; nt < 8; nt++) {
            float p0 = tf32r(__expf(s_[nt][0] - nm0));
            float p1 = tf32r(__expf(s_[nt][1] - nm0));
            float p2 = tf32r(__expf(s_[nt][2] - nm1));
            float p3 = tf32r(__expf(s_[nt][3] - nm1));
            rs0 += p0 + p1;
            rs1 += p2 + p3;
            const int c = nt * 8 + 2 * t;
            *(float2*)(Ps + (warpQ + g) * PSTR + c)     = make_float2(p0, p1);
            *(float2*)(Ps + (warpQ + g + 8) * PSTR + c) = make_float2(p2, p3);
        }
        rs0 += __shfl_xor_sync(0xffffffffu, rs0, 1);
        rs0 += __shfl_xor_sync(0xffffffffu, rs0, 2);
        rs1 += __shfl_xor_sync(0xffffffffu, rs1, 1);
        rs1 += __shfl_xor_sync(0xffffffffu, rs1, 2);
        l0 = l0 * corr0 + rs0;
        l1 = l1 * corr1 + rs1;

        #pragma unroll
        for (int nt = 0; nt < 8; nt++) {
            o[nt][0] *= corr0; o[nt][1] *= corr0;
            o[nt][2] *= corr1; o[nt][3] *= corr1;
        }
        __syncwarp();   // Ps rows are warp-private; only need warp visibility

        // stage 2: O += P V  (warp: 16q x 64d, k=64 keys)
        #pragma unroll
        for (int ks = 0; ks < 8; ks++) {
            const int kk = ks * 8 + t;
            const int r  = warpQ + g;
            uint32_t a0 = f2u(Ps[r * PSTR + kk]);
            uint32_t a1 = f2u(Ps[(r + 8) * PSTR + kk]);
            uint32_t a2 = f2u(Ps[r * PSTR + kk + 4]);
            uint32_t a3 = f2u(Ps[(r + 8) * PSTR + kk + 4]);
            #pragma unroll
            for (int nt = 0; nt < 8; nt++) {
                const int n = nt * 8 + g;
                uint32_t b0 = f2u(Vs[(ks * 8 + t) * VSTR + n]);
                uint32_t b1 = f2u(Vs[(ks * 8 + t + 4) * VSTR + n]);
                mma8(o[nt], a0, a1, a2, a3, b0, b1);
            }
        }
    }

    // normalize + store
    const float inv0 = 1.0f / l0;
    const float inv1 = 1.0f / l1;
    const int n0 = q0 + warpQ + g;
    float* po0 = out + ((size_t)bi * N_ + n0) * DIM_ + h * HD_;
    float* po1 = out + ((size_t)bi * N_ + n0 + 8) * DIM_ + h * HD_;
    #pragma unroll
    for (int nt = 0; nt < 8; nt++) {
        const int c = nt * 8 + 2 * t;
        *(float2*)(po0 + c) = make_float2(o[nt][0] * inv0, o[nt][1] * inv0);
        *(float2*)(po1 + c) = make_float2(o[nt][2] * inv1, o[nt][3] * inv1);
    }
}

// ---------------------------------------------------------------------------
extern "C" void kernel_launch(void* const* d_in, const int* in_sizes, int n_in,
                              void* d_out, int out_size)
{
    const float* x    = (const float*)d_in[0];
    const float* wqkv = (const float*)d_in[1];
    const float* bqkv = (const float*)d_in[2];
    float* out = (float*)d_out;

    float *xr, *wr;
    cudaGetSymbolAddress((void**)&xr, g_xr);
    cudaGetSymbolAddress((void**)&wr, g_wr);

    cudaFuncSetAttribute(qkv_mma_kernel,
                         cudaFuncAttributeMaxDynamicSharedMemorySize, G_SMEM_BYTES);
    cudaFuncSetAttribute(attn_kernel3,
                         cudaFuncAttributeMaxDynamicSharedMemorySize, ATT_SMEM);

    // 1) round X, W to tf32
    int n4x = (M_ * DIM_) / 4;
    int n4w = (E3_ * DIM_) / 4;
    round_tf32_kernel<<<(n4x + 255) / 256, 256>>>((const float4*)x, (float4*)xr, n4x);
    round_tf32_kernel<<<(n4w + 255) / 256, 256>>>((const float4*)wqkv, (float4*)wr, n4w);

    // 2) QKV projection (tensor cores, mma.sync tf32)
    dim3 ggrid(E3_ / 128, M_ / 128);   // (24, 64)
    qkv_mma_kernel<<<ggrid, 256, G_SMEM_BYTES>>>(xr, wr, bqkv);

    // 3) flash attention (tensor cores, mma.sync tf32)
    dim3 agrid(N_ / 128, B_ * H_);     // (16, 64)
    attn_kernel3<<<agrid, 256, ATT_SMEM>>>(out);
}